// round 8
// baseline (speedup 1.0000x reference)
#include <cuda_runtime.h>
#include <cuda_fp16.h>
#include <math.h>
#include <cstdint>

// ---------------- problem constants ----------------
#define Bn 2
#define Tn 4096
#define Dn 1024
#define Hn 16
#define KDn 512
#define VDn 1024
#define HKn 32
#define HVn 64
#define CHUNKn 64
#define NC (Tn / CHUNKn)          // 64 chunks
#define NTOK (Bn * Tn)            // 8192 tokens
#define BH (Bn * Hn)              // 32
#define NCB (NC * BH)             // 2048 chunk-heads
#define SCALE_Q 0.17677669529663687f  // 1/sqrt(32)

// ---------------- scratch (static device globals; no allocation) ----------------
__device__ float d_Q[NTOK * KDn];        // 16 MB
__device__ float d_Kb[NTOK * KDn];       // 16 MB
__device__ float d_Vb[NTOK * VDn];       // 32 MB
__device__ float d_Gb[NTOK * VDn];       // 32 MB
__device__ float d_GK[NTOK * KDn];       // 16 MB
__device__ float d_t16[NTOK * 16];       // 0.5 MB
__device__ float d_M[NCB * HKn * HVn];   // 16 MB
__device__ float d_Sb[NCB * HKn * HVn];  // 16 MB
__device__ float d_dl[NCB * HKn];        // 0.25 MB
__device__ float d_O[NTOK * VDn];        // 32 MB   intra-chunk o
__device__ __half d_Xh[NTOK * Dn];       // 16 MB   x in fp16
__device__ __half d_Oh[NTOK * VDn];      // 16 MB   gated o in fp16 (Wo input)
__device__ __half d_WqT[KDn * Dn];       // 1 MB    transposed fp16 weights (K-major)
__device__ __half d_WkT[KDn * Dn];       // 1 MB
__device__ __half d_WvT[VDn * Dn];       // 2 MB
__device__ __half d_WgT[VDn * Dn];       // 2 MB
__device__ __half d_WoT[Dn * Dn];        // 2 MB

// ---------------- helpers ----------------
__device__ __forceinline__ void mma_f16(float* c, const uint32_t* a, const uint32_t* b) {
    asm volatile(
        "mma.sync.aligned.m16n8k16.row.col.f32.f16.f16.f32 "
        "{%0,%1,%2,%3}, {%4,%5,%6,%7}, {%8,%9}, {%0,%1,%2,%3};"
        : "+f"(c[0]), "+f"(c[1]), "+f"(c[2]), "+f"(c[3])
        : "r"(a[0]), "r"(a[1]), "r"(a[2]), "r"(a[3]), "r"(b[0]), "r"(b[1]));
}
__device__ __forceinline__ void ldsm_x4(uint32_t* d, uint32_t addr) {
    asm volatile("ldmatrix.sync.aligned.m8n8.x4.shared.b16 {%0,%1,%2,%3}, [%4];"
        : "=r"(d[0]), "=r"(d[1]), "=r"(d[2]), "=r"(d[3]) : "r"(addr));
}
__device__ __forceinline__ void ldsm_x2(uint32_t* d, uint32_t addr) {
    asm volatile("ldmatrix.sync.aligned.m8n8.x2.shared.b16 {%0,%1}, [%2];"
        : "=r"(d[0]), "=r"(d[1]) : "r"(addr));
}

#define GST 3
#define STAGE_BYTES 32768   // A 16KB + B 16KB
#define GEMM_DYNSMEM (GST * STAGE_BYTES)

// shared mainloop body for the fp16 GEMM (tile 128x128, K-step 64 halves)
#define GEMM_BODY(Aptr, BTptr, Cptr, Kc, Nc)                                           \
    extern __shared__ __align__(16) char dyn[];                                        \
    uint32_t sbase;                                                                    \
    asm("{ .reg .u64 t; cvta.to.shared.u64 t, %1; cvt.u32.u64 %0, t; }"                \
        : "=r"(sbase) : "l"(dyn));                                                     \
    const int t = threadIdx.x;                                                         \
    const int lane = t & 31;                                                           \
    const int wrow = (t >> 5) >> 2;                                                    \
    const int wcol = (t >> 5) & 3;                                                     \
    const int NT = (Kc) >> 6;                                                          \
    const int aoff = (wrow * 64 + ((lane >> 3) & 1) * 8 + (lane & 7)) * 128            \
                   + ((lane >> 4) & 1) * 16;                                           \
    const int boff = (wcol * 32 + (lane & 7)) * 128                                    \
                   + ((lane >> 3) & 1) * 16;                                           \
    float acc[4][4][4];                                                                \
    _Pragma("unroll")                                                                  \
    for (int i = 0; i < 4; i++)                                                        \
        _Pragma("unroll")                                                              \
        for (int j = 0; j < 4; j++)                                                    \
            _Pragma("unroll")                                                          \
            for (int e = 0; e < 4; e++) acc[i][j][e] = 0.f;                            \
    LOAD_TILE(Aptr, BTptr, Kc, 0);                                                     \
    LOAD_TILE(Aptr, BTptr, Kc, 1);                                                     \
    for (int kt = 0; kt < NT; kt++) {                                                  \
        asm volatile("cp.async.wait_group %0;" :: "n"(GST - 2));                       \
        __syncthreads();                                                               \
        const int nt_ = kt + GST - 1;                                                  \
        if (nt_ < NT) LOAD_TILE(Aptr, BTptr, Kc, nt_);                                 \
        const uint32_t sAb = sbase + (kt % GST) * STAGE_BYTES;                         \
        const uint32_t sBb = sAb + 16384;                                              \
        _Pragma("unroll")                                                              \
        for (int ks = 0; ks < 4; ks++) {                                               \
            uint32_t af[4][4], bf[4][2];                                               \
            _Pragma("unroll")                                                          \
            for (int mt = 0; mt < 4; mt++) {                                           \
                int o = aoff + mt * 2048 + ks * 32;                                    \
                ldsm_x4(af[mt], sAb + (o ^ ((o >> 3) & 0x70)));                        \
            }                                                                          \
            _Pragma("unroll")                                                          \
            for (int nt = 0; nt < 4; nt++) {                                           \
                int o = boff + nt * 1024 + ks * 32;                                    \
                ldsm_x2(bf[nt], sBb + (o ^ ((o >> 3) & 0x70)));                        \
            }                                                                          \
            _Pragma("unroll")                                                          \
            for (int mt = 0; mt < 4; mt++)                                             \
                _Pragma("unroll")                                                      \
                for (int nt = 0; nt < 4; nt++)                                         \
                    mma_f16(acc[mt][nt], af[mt], bf[nt]);                              \
        }                                                                              \
    }                                                                                  \
    _Pragma("unroll")                                                                  \
    for (int mt = 0; mt < 4; mt++) {                                                   \
        _Pragma("unroll")                                                              \
        for (int nt = 0; nt < 4; nt++) {                                               \
            int r0 = bm + wrow * 64 + mt * 16 + (lane >> 2);                           \
            int c0 = bn + wcol * 32 + nt * 8 + (lane & 3) * 2;                         \
            float2 v0 = make_float2(acc[mt][nt][0], acc[mt][nt][1]);                   \
            float2 v1 = make_float2(acc[mt][nt][2], acc[mt][nt][3]);                   \
            *(float2*)&(Cptr)[(size_t)r0 * (Nc) + c0] = v0;                            \
            *(float2*)&(Cptr)[(size_t)(r0 + 8) * (Nc) + c0] = v1;                      \
        }                                                                              \
    }

#define LOAD_TILE(Aptr, BTptr, Kc, kt)                                                 \
    do {                                                                               \
        const int k0_ = (kt) << 6;                                                     \
        const uint32_t stg_ = sbase + ((kt) % GST) * STAGE_BYTES;                      \
        _Pragma("unroll")                                                              \
        for (int i_ = 0; i_ < 4; i_++) {                                               \
            int q_ = t + (i_ << 8);                                                    \
            int row_ = q_ >> 3, c16_ = q_ & 7;                                         \
            const __half* g_ = (Aptr) + (size_t)(bm + row_) * (Kc) + k0_ + (c16_ << 3);\
            uint32_t off_ = (uint32_t)((row_ << 7) + (c16_ << 4));                     \
            uint32_t dst_ = stg_ + (off_ ^ ((off_ >> 3) & 0x70));                      \
            asm volatile("cp.async.cg.shared.global [%0], [%1], 16;" :: "r"(dst_), "l"(g_)); \
        }                                                                              \
        _Pragma("unroll")                                                              \
        for (int i_ = 4; i_ < 8; i_++) {                                               \
            int q_ = t + (i_ << 8) - 1024;                                             \
            int row_ = q_ >> 3, c16_ = q_ & 7;                                         \
            const __half* g_ = (BTptr) + (size_t)(bn + row_) * (Kc) + k0_ + (c16_ << 3);\
            uint32_t off_ = (uint32_t)((row_ << 7) + (c16_ << 4));                     \
            uint32_t dst_ = stg_ + 16384 + (off_ ^ ((off_ >> 3) & 0x70));              \
            asm volatile("cp.async.cg.shared.global [%0], [%1], 16;" :: "r"(dst_), "l"(g_)); \
        }                                                                              \
        asm volatile("cp.async.commit_group;");                                        \
    } while (0)

// ---------------- merged Q/K/V/G projection GEMM (one launch) ----------------
struct ProjPtrs {
    const __half *wq, *wk, *wv, *wg;
    float *q, *k, *v, *g;
};

__global__ __launch_bounds__(256, 2) void gemm_proj(const __half* __restrict__ A,
                                                    ProjPtrs p)
{
    // flat x: 0..3 Wq | 4..7 Wk | 8..15 Wv | 16..23 Wg   (128-col tiles)
    const int xz = blockIdx.x;
    const __half* BT;
    float* C;
    int Nw, bnl;
    if (xz < 4)       { BT = p.wq; C = p.q; Nw = KDn; bnl = xz; }
    else if (xz < 8)  { BT = p.wk; C = p.k; Nw = KDn; bnl = xz - 4; }
    else if (xz < 16) { BT = p.wv; C = p.v; Nw = VDn; bnl = xz - 8; }
    else              { BT = p.wg; C = p.g; Nw = VDn; bnl = xz - 16; }
    const int bm = blockIdx.y << 7;
    const int bn = bnl << 7;
    GEMM_BODY(A, BT, C, Dn, Nw)
}

// ---------------- generic fp16 GEMM (used for Wo) ----------------
__global__ __launch_bounds__(256, 2) void gemm_f16(
    const __half* __restrict__ A, const __half* __restrict__ BT,
    float* __restrict__ C, int M, int N, int K)
{
    const int bm = blockIdx.y << 7, bn = blockIdx.x << 7;
    GEMM_BODY(A, BT, C, K, N)
}

// ---------------- pre-passes ----------------
__global__ __launch_bounds__(256) void conv_x_kernel(const float* __restrict__ X,
                                                     __half* __restrict__ Y)
{
    int i = blockIdx.x * 256 + threadIdx.x;   // over float4s
    float4 v = ((const float4*)X)[i];
    __half2 lo = __floats2half2_rn(v.x, v.y);
    __half2 hi = __floats2half2_rn(v.z, v.w);
    ((uint2*)Y)[i] = make_uint2(*(uint32_t*)&lo, *(uint32_t*)&hi);
}

// merged transpose of all 5 weights (flat 32x32-tile grid)
struct TransPtrs {
    const float *wq, *wk, *wv, *wg, *wo;
    __half *qT, *kT, *vT, *gT, *oT;
};

__global__ __launch_bounds__(256) void transpose_all(TransPtrs p)
{
    __shared__ float tl[32][33];
    // tiles: Wq 0..511 | Wk 512..1023 | Wv 1024..2047 | Wg 2048..3071 | Wo 3072..4095
    int bx = blockIdx.x;
    const float* W;
    __half* WT;
    int Kd, Nd, loc;
    if (bx < 512)       { W = p.wq; WT = p.qT; Kd = Dn;  Nd = KDn; loc = bx; }
    else if (bx < 1024) { W = p.wk; WT = p.kT; Kd = Dn;  Nd = KDn; loc = bx - 512; }
    else if (bx < 2048) { W = p.wv; WT = p.vT; Kd = Dn;  Nd = VDn; loc = bx - 1024; }
    else if (bx < 3072) { W = p.wg; WT = p.gT; Kd = Dn;  Nd = VDn; loc = bx - 2048; }
    else                { W = p.wo; WT = p.oT; Kd = VDn; Nd = Dn;  loc = bx - 3072; }
    const int nT = Nd >> 5;
    const int n0 = (loc % nT) * 32, k0 = (loc / nT) * 32;
    int tx = threadIdx.x & 31, ty = threadIdx.x >> 5;   // 32x8
    #pragma unroll
    for (int r = 0; r < 32; r += 8)
        tl[ty + r][tx] = W[(size_t)(k0 + ty + r) * Nd + n0 + tx];
    __syncthreads();
    #pragma unroll
    for (int r = 0; r < 32; r += 8)
        WT[(size_t)(n0 + ty + r) * Kd + k0 + tx] = __float2half_rn(tl[tx][ty + r]);
}

// ---------------- gk low-rank stage 1: t16 = x @ Wgk1 (fp32) ----------
__global__ __launch_bounds__(256) void gemm_gk1(const float* __restrict__ X,
                                                const float* __restrict__ W)
{
    __shared__ float red[256];
    const int m = blockIdx.x;
    const int tx = threadIdx.x & 15;
    const int ty = threadIdx.x >> 4;
    float acc = 0.f;
    const float* xr = X + (size_t)m * Dn;
    for (int k = ty; k < Dn; k += 16)
        acc += xr[k] * W[k * 16 + tx];
    red[threadIdx.x] = acc;
    __syncthreads();
    for (int s = 8; s > 0; s >>= 1) {
        if (ty < s) red[ty * 16 + tx] += red[(ty + s) * 16 + tx];
        __syncthreads();
    }
    if (ty == 0) d_t16[m * 16 + tx] = red[tx];
}

// ---------------- gk stage 2 ----------------
__global__ __launch_bounds__(256) void gk_kernel(const float* __restrict__ W2,
                                                 const float* __restrict__ bgk)
{
    int idx = blockIdx.x * blockDim.x + threadIdx.x;
    int m = idx >> 9;
    int n = idx & 511;
    const float* t = d_t16 + m * 16;
    float z = bgk[n];
    #pragma unroll
    for (int k = 0; k < 16; k++) z += t[k] * W2[k * KDn + n];
    float ls = fminf(z, 0.f) - log1pf(expf(-fabsf(z)));
    d_GK[idx] = ls * (1.f / 16.f);
}

// ---------------- attention phase A ----------------
__global__ __launch_bounds__(256) void attn_chunk_kernel()
{
    __shared__ float s_qe[2048];
    __shared__ float s_kd[2048];
    __shared__ float s_v[4096];
    __shared__ float s_A[2048];
    __shared__ float s_bl[32], s_dl[32];

    const int cb = blockIdx.x;
    const int bh = cb & 31, c = cb >> 5;
    const int b = bh >> 4, h = bh & 15;
    const int t = threadIdx.x;
    const size_t tok0 = (size_t)b * Tn + (size_t)c * CHUNKn;

    for (int e = t; e < 2048; e += 256) {
        int i = e >> 5, k = e & 31;
        s_qe[e] = d_GK[(tok0 + i) * KDn + h * HKn + k];
    }
    __syncthreads();
    if (t < 32) {
        float run = 0.f;
        for (int i = 0; i < 64; i++) { run += s_qe[i * 32 + t]; s_qe[i * 32 + t] = run; }
        s_bl[t] = run;
        s_dl[t] = expf(run);
    }
    __syncthreads();
    for (int e = t; e < 2048; e += 256) {
        int i = e >> 5, k = e & 31;
        float bb = s_qe[e];
        float kv = d_Kb[(tok0 + i) * KDn + h * HKn + k];
        s_kd[i * 32 + ((k ^ i) & 31)] = kv * expf(-bb);
        float qv = d_Q[(tok0 + i) * KDn + h * HKn + k];
        s_qe[e] = qv * expf(bb) * SCALE_Q;
    }
    for (int e = t; e < 4096; e += 256) {
        int i = e >> 6, v = e & 63;
        s_v[e] = d_Vb[(tok0 + i) * VDn + h * HVn + v];
    }
    __syncthreads();
    for (int o = t; o < 2048; o += 256) {
        int k = o >> 6, v = o & 63;
        float acc = 0.f;
        #pragma unroll 8
        for (int j = 0; j < 64; j++)
            acc += s_kd[j * 32 + ((k ^ j) & 31)] * s_v[j * 64 + v];
        d_M[(size_t)cb * 2048 + o] = acc * s_dl[k];
    }
    if (t < 32) d_dl[cb * 32 + t] = s_dl[t];

    #pragma unroll
    for (int half = 0; half < 2; half++) {
        __syncthreads();
        for (int o = t; o < 2048; o += 256) {
            int il = o >> 6, j = o & 63;
            int i = half * 32 + il;
            float acc = 0.f;
            if (j <= i) {
                #pragma unroll
                for (int k = 0; k < 32; k++)
                    acc += s_qe[i * 32 + k] * s_kd[j * 32 + ((k ^ j) & 31)];
            }
            s_A[o] = acc;
        }
        __syncthreads();
        for (int o = t; o < 2048; o += 256) {
            int il = o >> 6, v = o & 63;
            int i = half * 32 + il;
            float acc = 0.f;
            #pragma unroll 8
            for (int j = 0; j < 64; j++)
                acc += s_A[il * 64 + j] * s_v[j * 64 + v];
            d_O[(tok0 + i) * VDn + h * HVn + v] = acc;
        }
    }
}

// ---------------- attention phase B: serial state scan (128 blocks) -----------
__global__ __launch_bounds__(512) void scan_kernel()
{
    const int bh = blockIdx.x >> 2;                 // 0..31
    const int idx = (blockIdx.x & 3) * 512 + threadIdx.x;   // 0..2047
    float S = 0.f;
    for (int c = 0; c < NC; c++) {
        const int ch = c * 32 + bh;
        const size_t base = (size_t)ch * 2048;
        d_Sb[base + idx] = S;
        S = d_dl[ch * 32 + (idx >> 6)] * S + d_M[base + idx];
    }
}

// ---------------- attention phase C: inter-chunk + RMSNorm + SiLU gate ------------
// 16 threads per row (half-warp); RMS via shfl only — no syncthreads in the loop.
__global__ __launch_bounds__(256) void attn_inter_kernel(const float* __restrict__ norm_w)
{
    __shared__ float s_qe[2048];
    __shared__ float s_S[2048];

    const int cb = blockIdx.x;
    const int bh = cb & 31, c = cb >> 5;
    const int b = bh >> 4, h = bh & 15;
    const int t = threadIdx.x;
    const size_t tok0 = (size_t)b * Tn + (size_t)c * CHUNKn;

    for (int e = t; e < 2048; e += 256)
        s_qe[e] = d_GK[(tok0 + (e >> 5)) * KDn + h * HKn + (e & 31)];
    for (int e = t; e < 2048; e += 256)
        s_S[e] = d_Sb[(size_t)cb * 2048 + e];
    __syncthreads();
    if (t < 32) {
        float run = 0.f;
        for (int i = 0; i < 64; i++) { run += s_qe[i * 32 + t]; s_qe[i * 32 + t] = run; }
    }
    __syncthreads();
    for (int e = t; e < 2048; e += 256) {
        float bb = s_qe[e];
        float qv = d_Q[(tok0 + (e >> 5)) * KDn + h * HKn + (e & 31)];
        s_qe[e] = qv * expf(bb) * SCALE_Q;
    }
    __syncthreads();

    const float nw0 = norm_w[(t & 15) * 4 + 0];
    const float nw1 = norm_w[(t & 15) * 4 + 1];
    const float nw2 = norm_w[(t & 15) * 4 + 2];
    const float nw3 = norm_w[(t & 15) * 4 + 3];

    #pragma unroll
    for (int r = 0; r < 4; r++) {
        int i = r * 16 + (t >> 4);          // row 0..63
        int v4 = (t & 15) * 4;              // v-lane base
        size_t gi = (tok0 + i) * VDn + h * HVn + v4;
        float4 o4 = *(const float4*)&d_O[gi];
        float a0 = o4.x, a1 = o4.y, a2 = o4.z, a3 = o4.w;
        #pragma unroll
        for (int k = 0; k < 32; k++) {
            float q = s_qe[i * 32 + k];
            const float4 s4 = *(const float4*)&s_S[k * 64 + v4];
            a0 += q * s4.x; a1 += q * s4.y; a2 += q * s4.z; a3 += q * s4.w;
        }
        float ss = a0 * a0 + a1 * a1 + a2 * a2 + a3 * a3;
        ss += __shfl_xor_sync(0xffffffffu, ss, 8);
        ss += __shfl_xor_sync(0xffffffffu, ss, 4);
        ss += __shfl_xor_sync(0xffffffffu, ss, 2);
        ss += __shfl_xor_sync(0xffffffffu, ss, 1);
        float rinv = rsqrtf(ss * (1.f / 64.f) + 1e-5f);
        float4 g4 = *(const float4*)&d_Gb[gi];
        float sg0 = g4.x / (1.f + expf(-g4.x));
        float sg1 = g4.y / (1.f + expf(-g4.y));
        float sg2 = g4.z / (1.f + expf(-g4.z));
        float sg3 = g4.w / (1.f + expf(-g4.w));
        __half2 lo = __floats2half2_rn(a0 * rinv * nw0 * sg0, a1 * rinv * nw1 * sg1);
        __half2 hi = __floats2half2_rn(a2 * rinv * nw2 * sg2, a3 * rinv * nw3 * sg3);
        *(uint2*)&d_Oh[gi] = make_uint2(*(uint32_t*)&lo, *(uint32_t*)&hi);
    }
}

// ---------------- launch ----------------
extern "C" void kernel_launch(void* const* d_in, const int* in_sizes, int n_in,
                              void* d_out, int out_size)
{
    const float* x      = (const float*)d_in[0];
    const float* Wq     = (const float*)d_in[1];
    const float* Wk     = (const float*)d_in[2];
    const float* Wv     = (const float*)d_in[3];
    const float* Wgk1   = (const float*)d_in[4];
    const float* Wgk2   = (const float*)d_in[5];
    const float* bgk    = (const float*)d_in[6];
    const float* Wg     = (const float*)d_in[7];
    const float* norm_w = (const float*)d_in[8];
    const float* Wo     = (const float*)d_in[9];
    float* out = (float*)d_out;

    float *pQ, *pK, *pV, *pG;
    __half *pXh, *pOh, *pWqT, *pWkT, *pWvT, *pWgT, *pWoT;
    cudaGetSymbolAddress((void**)&pQ, d_Q);
    cudaGetSymbolAddress((void**)&pK, d_Kb);
    cudaGetSymbolAddress((void**)&pV, d_Vb);
    cudaGetSymbolAddress((void**)&pG, d_Gb);
    cudaGetSymbolAddress((void**)&pXh, d_Xh);
    cudaGetSymbolAddress((void**)&pOh, d_Oh);
    cudaGetSymbolAddress((void**)&pWqT, d_WqT);
    cudaGetSymbolAddress((void**)&pWkT, d_WkT);
    cudaGetSymbolAddress((void**)&pWvT, d_WvT);
    cudaGetSymbolAddress((void**)&pWgT, d_WgT);
    cudaGetSymbolAddress((void**)&pWoT, d_WoT);

    cudaFuncSetAttribute(gemm_proj, cudaFuncAttributeMaxDynamicSharedMemorySize,
                         GEMM_DYNSMEM);
    cudaFuncSetAttribute(gemm_f16, cudaFuncAttributeMaxDynamicSharedMemorySize,
                         GEMM_DYNSMEM);

    // pre-passes: fp16 conversion + all weight transposes in one launch
    conv_x_kernel<<<(NTOK * Dn / 4) / 256, 256>>>(x, pXh);
    TransPtrs tp{Wq, Wk, Wv, Wg, Wo, pWqT, pWkT, pWvT, pWgT, pWoT};
    transpose_all<<<4096, 256>>>(tp);

    // all four projections in ONE launch (wave-packed)
    ProjPtrs pp{pWqT, pWkT, pWvT, pWgT, pQ, pK, pV, pG};
    gemm_proj<<<dim3(24, NTOK / 128), 256, GEMM_DYNSMEM>>>(pXh, pp);

    // gate path (fp32 throughout)
    gemm_gk1<<<NTOK, 256>>>(x, Wgk1);
    gk_kernel<<<(NTOK * KDn) / 256, 256>>>(Wgk2, bgk);

    // chunked linear attention
    attn_chunk_kernel<<<NCB, 256>>>();
    scan_kernel<<<BH * 4, 512>>>();
    attn_inter_kernel<<<NCB, 256>>>(norm_w);

    // output projection
    gemm_f16<<<dim3(Dn / 128, NTOK / 128), 256, GEMM_DYNSMEM>>>(pOh, pWoT, out, NTOK, Dn, Dn);
}